// round 5
// baseline (speedup 1.0000x reference)
#include <cuda_runtime.h>

#define NN   128
#define FIN  512
#define EE   128
#define H1D  256
#define H2D  128
#define TPB  512

typedef unsigned long long ull;

__device__ __forceinline__ ull ffma2(ull a, ull b, ull c){
    ull d;
    asm("fma.rn.f32x2 %0, %1, %2, %3;" : "=l"(d) : "l"(a), "l"(b), "l"(c));
    return d;
}
__device__ __forceinline__ ull packff(float x){
    ull d; asm("mov.b64 %0, {%1, %2};" : "=l"(d) : "f"(x), "f"(x)); return d;
}

// ---------------- persistent device state ----------------------------------
__device__ float g_P[NN*EE];
__device__ float g_feat0[NN*EE];
__device__ float g_A0[NN*H1D];
__device__ float g_G0[NN*H1D];
__device__ float g_G[NN*H1D];
__device__ float g_feat[NN*EE];
__device__ int   g_cand[NN*4];
__device__ int   g_ccnt[NN];
__device__ int   g_upd[NN];
__device__ ull   g_mL[NN], g_mH[NN];
__device__ int   g_group[NN*4];
__device__ int   g_gc[NN];
__device__ int   g_ngroups;

// ---------------- initA: 4 nodes per block, exact per-output order ----------
__global__ void initA_kernel(const float* __restrict__ fo, const float* __restrict__ We,
                             const float* __restrict__ be, const float* __restrict__ adj)
{
    __shared__ float fos[4][FIN];
    __shared__ unsigned bal[4][4];
    int m = threadIdx.x >> 7;            // node within block
    int e = threadIdx.x & 127;
    int i = blockIdx.x*4 + m;
    // stage 4 fo rows (each 128-thread slice loads its row as float4)
    ((float4*)fos[m])[e] = ((const float4*)(fo + i*FIN))[e];
    unsigned b = __ballot_sync(0xffffffffu, adj[i*NN + e] != 0.0f);
    if ((e & 31) == 0) bal[m][e >> 5] = b;
    __syncthreads();

    float s = 0.f;
    #pragma unroll 16
    for (int f = 0; f < FIN; f++) s += fos[m][f] * We[f*EE + e];
    g_P[i*EE+e] = s;
    float f0 = fmaxf(s + be[e], 0.f);
    g_feat0[i*EE+e] = f0;
    g_feat [i*EE+e] = f0;

    if (e == 0) {
        g_upd[i] = 0;
        int c = 0; ull ml = 0, mh = 0;
        if (i < 64) ml |= 1ull << i; else mh |= 1ull << (i-64);
        for (int wq = 0; wq < 4; wq++){
            unsigned bb = bal[m][wq];
            while (bb){
                int bit = __ffs(bb) - 1; bb &= bb - 1;
                int vtx = wq*32 + bit;
                if (c < 4) g_cand[i*4 + c] = vtx;
                c++;
                if (vtx < 64) ml |= 1ull << vtx; else mh |= 1ull << (vtx-64);
            }
        }
        if (c > 3) c = 3;                              // K=3 -> <=3 distinct
        g_ccnt[i] = c;
        g_mL[i] = ml; g_mH[i] = mh;
    }
}

// ---------------- initB: A0/G0/G -------------------------------------------
__global__ void initB_kernel(const float* __restrict__ W1)
{
    __shared__ float fs[EE];
    int i = blockIdx.x, j = threadIdx.x;               // 256 threads
    if (j < EE) fs[j] = g_feat0[i*EE + j];
    __syncthreads();
    float st = 0.f, sb = 0.f;
    #pragma unroll 16
    for (int k = 0; k < EE; k++){
        float f = fs[k];
        st += f * W1[k*H1D + j];
        sb += f * W1[(EE+k)*H1D + j];
    }
    g_A0[i*H1D+j] = st;
    g_G0[i*H1D+j] = sb;
    g_G [i*H1D+j] = sb;
}

// ---------------- scheduler: levels (longest path) + groups of <=4 ----------
__global__ void sched_kernel()
{
    __shared__ ull mL[NN], mH[NN];
    __shared__ int lvl[NN], hist[NN], gb_[NN];
    int t = threadIdx.x;                               // 128 threads
    mL[t] = g_mL[t]; mH[t] = g_mH[t]; hist[t] = 0;
    #pragma unroll
    for (int q = 0; q < 4; q++) g_group[t*4 + q] = -1;
    __syncthreads();

    if (t < 32){
        for (int i = 0; i < NN; i++){
            ull aL = mL[i], aH = mH[i];
            int best = -1;
            #pragma unroll
            for (int q = 0; q < 4; q++){
                int j = t + q*32;
                if (j < i && (((mL[j]&aL) | (mH[j]&aH)) != 0ull))
                    best = max(best, lvl[j]);
            }
            #pragma unroll
            for (int off = 16; off; off >>= 1)
                best = max(best, __shfl_xor_sync(0xffffffffu, best, off));
            if (t == 0) lvl[i] = best + 1;
            __syncwarp();
        }
    }
    __syncthreads();

    int L = lvl[t];
    atomicAdd(&hist[L], 1);
    __syncthreads();
    if (t == 0){
        int gb = 0;
        for (int l = 0; l < NN; l++){ gb_[l] = gb; gb += (hist[l] + 3) >> 2; }
        g_ngroups = gb;
    }
    __syncthreads();
    int r = 0;
    for (int j = 0; j < NN; j++) r += (j < t && lvl[j] == L);
    int grp = gb_[L] + (r >> 2), slot = r & 3;
    g_group[grp*4 + slot] = t;
    if (slot == 0) g_gc[grp] = min(4, hist[L] - r);
}

// ---------------- S2 template: NPAIR = number of row-pairs ------------------
template<int NPAIR>
__device__ __forceinline__ void s2_compute(const ull* __restrict__ h1P,
                                           float2* __restrict__ part,
                                           const float (&w2a)[32], const float (&w2b)[32],
                                           int kslab, int j0)
{
    ull accA[NPAIR], accB[NPAIR];
    #pragma unroll
    for (int p = 0; p < NPAIR; p++){ accA[p] = 0ull; accB[p] = 0ull; }
    #pragma unroll
    for (int kk = 0; kk < 32; kk++){
        int k = kslab*32 + kk;
        ull wpa = packff(w2a[kk]), wpb = packff(w2b[kk]);
        #pragma unroll
        for (int p = 0; p < NPAIR; p++){
            ull hp = h1P[p*256 + k];
            accA[p] = ffma2(hp, wpa, accA[p]);
            accB[p] = ffma2(hp, wpb, accB[p]);
        }
    }
    #pragma unroll
    for (int p = 0; p < NPAIR; p++){
        float2 fa, fb;
        asm("mov.b64 {%0,%1}, %2;" : "=f"(fa.x), "=f"(fa.y) : "l"(accA[p]));
        asm("mov.b64 {%0,%1}, %2;" : "=f"(fb.x), "=f"(fb.y) : "l"(accB[p]));
        part[(p*8 + kslab)*128 + j0]     = fa;
        part[(p*8 + kslab)*128 + j0 + 1] = fb;
    }
}

// ---------------- main wave-parallel rollout: ONE CTA -----------------------
extern __shared__ float sm[];

__global__ void __launch_bounds__(TPB, 1) main_kernel(
    const float* __restrict__ W1, const float* __restrict__ W2,
    const float* __restrict__ b1, const float* __restrict__ b2,
    const float* __restrict__ wlk, const float* __restrict__ blk,
    const float* __restrict__ wact, const float* __restrict__ bact,
    const float* __restrict__ be, float* __restrict__ out)
{
    // dynamic smem layout
    float* base_ = sm;
    ull*    h1P  = (ull*)base_;          base_ += 4096;    // 8 pairs x 256 k (ull)
    float2* part = (float2*)base_;       base_ += 16384;   // [pair][ks][j] float2
    float*  dual = base_;                base_ += 8192;    // [m][ks][j]
    float*  dualB= base_;                base_ += 8192;
    float*  a_   = base_;                base_ += 1024;    // [m][256]
    float*  curx = base_;                base_ += 512;     // [m][128]
    float*  selP = base_;                base_ += 512;
    float*  Pis  = base_;                base_ += 512;
    float*  b1s  = base_;                base_ += 256;
    float*  b2s  = base_;                base_ += 128;
    float*  wlks = base_;                base_ += 128;
    float*  wa0  = base_;                base_ += 128;
    float*  wa1  = base_;                base_ += 128;
    float*  bes  = base_;                base_ += 128;

    __shared__ float s_lk[16], s_a0[16], s_a1[16];
    __shared__ float s_cntv[4], s_den[4];
    __shared__ int   s_alive[4][3], s_na[4], s_done[4], s_vsel[4], s_at[4];
    __shared__ int   s_sel[4], s_needgi[4], s_gdirty[4], s_nid[4];
    __shared__ int   s_cont, s_needB, s_flush, s_P;
    __shared__ float s_blk, s_ba0, s_ba1;

    const int tid  = threadIdx.x;
    const int w    = tid >> 5;
    const int lane = tid & 31;
    const int kslab = w >> 1, jh = w & 1;
    const int j0 = jh*64 + lane*2;

    if (tid < H1D) b1s[tid] = b1[tid];
    if (tid < H2D){ b2s[tid]=b2[tid]; wlks[tid]=wlk[tid];
                    wa0[tid]=wact[2*tid]; wa1[tid]=wact[2*tid+1]; }
    if (tid < EE)  bes[tid] = be[tid];
    if (tid == 0){ s_blk=blk[0]; s_ba0=bact[0]; s_ba1=bact[1]; }

    float w2a[32], w2b[32];
    #pragma unroll
    for (int kk = 0; kk < 32; kk++){
        float2 v = *(const float2*)(W2 + (kslab*32+kk)*H2D + j0);
        w2a[kk] = v.x; w2b[kk] = v.y;
    }
    int ngroups = g_ngroups;
    __syncthreads();

    for (int g = 0; g < ngroups; g++){
        // ---- wave init ----
        if (tid < 4){
            int m = tid;
            int nid = g_group[g*4 + m];
            s_nid[m] = nid;
            if (nid >= 0){
                int c = g_ccnt[nid]; s_na[m] = c;
                for (int q = 0; q < c; q++) s_alive[m][q] = g_cand[nid*4 + q];
                s_done[m] = 0; s_cntv[m] = 0.f; s_gdirty[m] = 0; s_sel[m] = 0;
            } else { s_na[m] = 0; s_done[m] = 1; s_gdirty[m] = 0; s_sel[m] = 0; }
            if (m == 0){ s_cont = 1; s_P = 2 * g_gc[g]; }   // s_P = PAIR count
        }
        #pragma unroll
        for (int h = 0; h < 2; h++){
            int idx = h*512 + tid, m = idx >> 8, j = idx & 255;
            int nid = g_group[g*4 + m];
            a_[m*256 + j] = (nid >= 0) ? g_A0[nid*H1D + j] : 0.f;
        }
        {
            int m = tid >> 7, e = tid & 127;
            int nid = g_group[g*4 + m];
            curx[m*128+e] = 0.f; selP[m*128+e] = 0.f;
            Pis[m*128+e] = (nid >= 0) ? g_P[nid*EE + e] : 0.f;
        }
        __syncthreads();

        // ---- step loop ----
        for (int step = 0; step < 3; step++){
            if (!s_cont) break;

            // S1: pack h1 row-pairs (all 8 pairs; zeros for inactive slots)
            {
                int k = tid & 255, hi = tid >> 8;
                #pragma unroll
                for (int pp = 0; pp < 4; pp++){
                    int p = hi*4 + pp;
                    float v2[2];
                    #pragma unroll
                    for (int h2 = 0; h2 < 2; h2++){
                        int slot = p*2 + h2; int m = slot >> 2, r = slot & 3;
                        float val = 0.f;
                        int na = s_na[m];
                        if (!s_done[m] && na > 0){
                            float bb = a_[m*256 + k] + b1s[k];
                            if (r < na){
                                int v = s_alive[m][r];
                                float gg = (v > 0) ? g_G[v*H1D + k] : 0.f;  // `if v>0` quirk
                                val = fmaxf(bb + gg, 0.f);
                            } else if (r == na) val = fmaxf(bb, 0.f);       // sentinel
                        }
                        v2[h2] = val;
                    }
                    ull pk; asm("mov.b64 %0, {%1,%2};" : "=l"(pk) : "f"(v2[0]), "f"(v2[1]));
                    h1P[p*256 + k] = pk;
                }
            }
            __syncthreads();

            // S2 — template arg = PAIR COUNT (R4 bug: was halved)
            switch (s_P){
                case 2:  s2_compute<2>(h1P, part, w2a, w2b, kslab, j0); break;
                case 4:  s2_compute<4>(h1P, part, w2a, w2b, kslab, j0); break;
                case 6:  s2_compute<6>(h1P, part, w2a, w2b, kslab, j0); break;
                default: s2_compute<8>(h1P, part, w2a, w2b, kslab, j0); break;
            }
            __syncthreads();

            // S3: warp per slot
            {
                int slot = w, m = slot >> 2, r = slot & 3;
                if (s_nid[m] >= 0 && !s_done[m] && s_na[m] > 0 && r <= s_na[m]){
                    int pair = slot >> 1, el = slot & 1;
                    float lk = 0.f, p0 = 0.f, p1 = 0.f;
                    #pragma unroll
                    for (int q = 0; q < 4; q++){
                        int j = lane + q*32;
                        float ss = b2s[j];
                        #pragma unroll
                        for (int ks = 0; ks < 8; ks++){
                            float2 vv = part[(pair*8 + ks)*128 + j];
                            ss += el ? vv.y : vv.x;
                        }
                        float h = fmaxf(ss, 0.f);
                        lk += h*wlks[j]; p0 += h*wa0[j]; p1 += h*wa1[j];
                    }
                    #pragma unroll
                    for (int off = 16; off; off >>= 1){
                        lk += __shfl_xor_sync(0xffffffffu, lk, off);
                        p0 += __shfl_xor_sync(0xffffffffu, p0, off);
                        p1 += __shfl_xor_sync(0xffffffffu, p1, off);
                    }
                    if (lane == 0){ s_lk[slot]=lk+s_blk; s_a0[slot]=p0+s_ba0; s_a1[slot]=p1+s_ba1; }
                }
            }
            __syncthreads();

            // S4a: per-node decision (parallel over m; disjoint writes)
            if (tid < 4){
                int m = tid; s_sel[m] = 0;
                if (!s_done[m] && s_na[m] > 0){
                    int na = s_na[m], bse = m*4;
                    float best = -3.4028235e38f; int bi = -1;
                    for (int r = 0; r < na; r++)
                        if (s_lk[bse+r] > best){ best = s_lk[bse+r]; bi = r; }
                    if (s_lk[bse+na] > best){
                        s_done[m] = 1;
                    } else {
                        int v  = s_alive[m][bi];
                        int at = (s_a1[bse+bi] > s_a0[bse+bi]) ? 1 : 0;
                        s_vsel[m] = v; s_at[m] = at; s_sel[m] = 1;
                        s_den[m]  = s_cntv[m] + (float)at + 1.0f;
                        s_cntv[m] += (float)at;
                        for (int q = bi; q < na-1; q++) s_alive[m][q] = s_alive[m][q+1];
                        s_na[m] = na - 1;
                        int nid = s_nid[m];
                        int ng = 0;
                        for (int q = 0; q < na-1; q++) if (s_alive[m][q] == nid) ng = 1;
                        s_needgi[m] = ng;
                        s_gdirty[m] = (v == nid) ? 0 : 1;
                        g_upd[nid] = 1; g_upd[v] = 1;
                    }
                }
            }
            __syncthreads();

            // S4b + aggregates
            {
                if (tid == 0){
                    int c = 0, nB = 0, mm = 0;
                    for (int m = 0; m < 4; m++){
                        if (!s_done[m] && s_na[m] > 0){ c = 1; mm = m + 1; }
                        if (s_sel[m] && s_needgi[m]) nB = 1;
                    }
                    s_cont = c; s_needB = nB; s_P = 2*mm;   // pairs for next step
                }
                int m = tid >> 7, e = tid & 127;
                if (s_sel[m]){
                    int nid = s_nid[m], v = s_vsel[m];
                    float atf = (float)s_at[m], denom = s_den[m];
                    float pv = g_P[v*EE + e], pi = Pis[m*128 + e];
                    float nx = fmaxf((selP[m*128+e] + atf*pv + pi)/denom + bes[e], 0.f);
                    if (s_at[m]) selP[m*128+e] += pv;
                    float f0v = g_feat0[v*EE + e];
                    g_feat[v*EE + e] = f0v;
                    float fx = (v == nid) ? f0v : nx;
                    g_feat[nid*EE + e] = fx;
                    curx[m*128 + e] = fx;
                }
                #pragma unroll
                for (int h = 0; h < 2; h++){
                    int idx = h*512 + tid, mm2 = idx >> 8, jj = idx & 255;
                    if (s_sel[mm2]) g_G[s_vsel[mm2]*H1D + jj] = g_G0[s_vsel[mm2]*H1D + jj];
                }
            }
            __syncthreads();
            if (!s_cont) break;
            if (step >= 2) break;          // a_ never needed again; flush covers G[i]

            // S5: batched a = curx @ W1_top (+ G[i] bottom stream if needed)
            {
                int jg = tid & 63, ks = tid >> 6;
                const float* bw = W1 + (ks*16)*H1D + jg*4;
                float4 a0 = make_float4(0,0,0,0), a1 = a0, a2 = a0, a3 = a0;
                #pragma unroll
                for (int kk = 0; kk < 16; kk++){
                    float4 wr = *(const float4*)(bw + kk*H1D);
                    float c0 = curx[0*128 + ks*16 + kk];
                    float c1 = curx[1*128 + ks*16 + kk];
                    float c2 = curx[2*128 + ks*16 + kk];
                    float c3 = curx[3*128 + ks*16 + kk];
                    a0.x += c0*wr.x; a0.y += c0*wr.y; a0.z += c0*wr.z; a0.w += c0*wr.w;
                    a1.x += c1*wr.x; a1.y += c1*wr.y; a1.z += c1*wr.z; a1.w += c1*wr.w;
                    a2.x += c2*wr.x; a2.y += c2*wr.y; a2.z += c2*wr.z; a2.w += c2*wr.w;
                    a3.x += c3*wr.x; a3.y += c3*wr.y; a3.z += c3*wr.z; a3.w += c3*wr.w;
                }
                *(float4*)(dual + (0*8 + ks)*H1D + jg*4) = a0;
                *(float4*)(dual + (1*8 + ks)*H1D + jg*4) = a1;
                *(float4*)(dual + (2*8 + ks)*H1D + jg*4) = a2;
                *(float4*)(dual + (3*8 + ks)*H1D + jg*4) = a3;
                if (s_needB){
                    const float* bwB = W1 + (EE + ks*16)*H1D + jg*4;
                    float4 e0 = make_float4(0,0,0,0), e1 = e0, e2 = e0, e3 = e0;
                    #pragma unroll
                    for (int kk = 0; kk < 16; kk++){
                        float4 wr = *(const float4*)(bwB + kk*H1D);
                        float c0 = curx[0*128 + ks*16 + kk];
                        float c1 = curx[1*128 + ks*16 + kk];
                        float c2 = curx[2*128 + ks*16 + kk];
                        float c3 = curx[3*128 + ks*16 + kk];
                        e0.x += c0*wr.x; e0.y += c0*wr.y; e0.z += c0*wr.z; e0.w += c0*wr.w;
                        e1.x += c1*wr.x; e1.y += c1*wr.y; e1.z += c1*wr.z; e1.w += c1*wr.w;
                        e2.x += c2*wr.x; e2.y += c2*wr.y; e2.z += c2*wr.z; e2.w += c2*wr.w;
                        e3.x += c3*wr.x; e3.y += c3*wr.y; e3.z += c3*wr.z; e3.w += c3*wr.w;
                    }
                    *(float4*)(dualB + (0*8 + ks)*H1D + jg*4) = e0;
                    *(float4*)(dualB + (1*8 + ks)*H1D + jg*4) = e1;
                    *(float4*)(dualB + (2*8 + ks)*H1D + jg*4) = e2;
                    *(float4*)(dualB + (3*8 + ks)*H1D + jg*4) = e3;
                }
            }
            __syncthreads();
            // reduce
            {
                #pragma unroll
                for (int h = 0; h < 2; h++){
                    int idx = h*512 + tid, m = idx >> 8, j = idx & 255;
                    float ssum = 0.f;
                    #pragma unroll
                    for (int ks = 0; ks < 8; ks++) ssum += dual[(m*8 + ks)*H1D + j];
                    a_[m*256 + j] = ssum;
                    if (s_needB && s_sel[m] && s_needgi[m]){
                        float sb = 0.f;
                        #pragma unroll
                        for (int ks = 0; ks < 8; ks++) sb += dualB[(m*8 + ks)*H1D + j];
                        g_G[s_nid[m]*H1D + j] = sb;
                    }
                }
                if (tid < 4 && s_sel[tid] && s_needgi[tid]) s_gdirty[tid] = 0;
            }
            __syncthreads();
        } // steps

        // ---- flush stale G[i] rows (batched bottom stream) ----
        if (tid == 0){
            int f = 0;
            for (int m = 0; m < 4; m++) if (s_gdirty[m]) f = 1;
            s_flush = f;
        }
        __syncthreads();
        if (s_flush){
            {
                int jg = tid & 63, ks = tid >> 6;
                const float* bwB = W1 + (EE + ks*16)*H1D + jg*4;
                float4 e0 = make_float4(0,0,0,0), e1 = e0, e2 = e0, e3 = e0;
                #pragma unroll
                for (int kk = 0; kk < 16; kk++){
                    float4 wr = *(const float4*)(bwB + kk*H1D);
                    float c0 = curx[0*128 + ks*16 + kk];
                    float c1 = curx[1*128 + ks*16 + kk];
                    float c2 = curx[2*128 + ks*16 + kk];
                    float c3 = curx[3*128 + ks*16 + kk];
                    e0.x += c0*wr.x; e0.y += c0*wr.y; e0.z += c0*wr.z; e0.w += c0*wr.w;
                    e1.x += c1*wr.x; e1.y += c1*wr.y; e1.z += c1*wr.z; e1.w += c1*wr.w;
                    e2.x += c2*wr.x; e2.y += c2*wr.y; e2.z += c2*wr.z; e2.w += c2*wr.w;
                    e3.x += c3*wr.x; e3.y += c3*wr.y; e3.z += c3*wr.z; e3.w += c3*wr.w;
                }
                *(float4*)(dual + (0*8 + ks)*H1D + jg*4) = e0;
                *(float4*)(dual + (1*8 + ks)*H1D + jg*4) = e1;
                *(float4*)(dual + (2*8 + ks)*H1D + jg*4) = e2;
                *(float4*)(dual + (3*8 + ks)*H1D + jg*4) = e3;
            }
            __syncthreads();
            #pragma unroll
            for (int h = 0; h < 2; h++){
                int idx = h*512 + tid, m = idx >> 8, j = idx & 255;
                if (s_gdirty[m]){
                    float sb = 0.f;
                    #pragma unroll
                    for (int ks = 0; ks < 8; ks++) sb += dual[(m*8 + ks)*H1D + j];
                    g_G[s_nid[m]*H1D + j] = sb;
                }
            }
            __syncthreads();
        }
    } // groups

    // output
    __syncthreads();
    for (int t = tid; t < NN*EE; t += TPB)
        out[t] = g_upd[t >> 7] ? g_feat[t] : 0.f;
}

// ---------------- launch ----------------------------------------------------
static const int DYN_SMEM = (4096 + 16384 + 8192 + 8192 + 1024 + 512*3
                             + 256 + 128*5) * (int)sizeof(float);

extern "C" void kernel_launch(void* const* d_in, const int* in_sizes, int n_in,
                              void* d_out, int out_size)
{
    const float* adj = (const float*)d_in[0];
    const float* fo  = (const float*)d_in[1];
    // d_in[2] = labels (unused)
    const float* We  = (const float*)d_in[3];
    const float* be  = (const float*)d_in[4];
    const float* W1  = (const float*)d_in[5];
    const float* b1  = (const float*)d_in[6];
    const float* W2  = (const float*)d_in[7];
    const float* b2  = (const float*)d_in[8];
    const float* wlk = (const float*)d_in[9];
    const float* blk = (const float*)d_in[10];
    const float* wac = (const float*)d_in[11];
    const float* bac = (const float*)d_in[12];
    float* out = (float*)d_out;

    cudaFuncSetAttribute(main_kernel, cudaFuncAttributeMaxDynamicSharedMemorySize, DYN_SMEM);

    initA_kernel<<<32, 512>>>(fo, We, be, adj);
    initB_kernel<<<NN, H1D>>>(W1);
    sched_kernel<<<1, 128>>>();
    main_kernel<<<1, TPB, DYN_SMEM>>>(W1, W2, b1, b2, wlk, blk, wac, bac, be, out);
}